// round 7
// baseline (speedup 1.0000x reference)
#include <cuda_runtime.h>
#include <cuda_fp16.h>

// Sinkhorn on s[B=32, N=1024, M=1024], MAX_ITER=15, EPS=1e-4.
//
// Single persistent kernel, factored form s_t = r_i * s0_ij * c_j.
// Block k of batch b owns rows [64k,64k+64); thread t owns columns
// [4t, 4t+4) for ALL phases, so c lives in 4 registers per thread and
// every sweep over the fp16 copy is row-contiguous uint2 loads.
// Row steps: per-thread 4-col dot -> warp shuffle reduce -> qw[row][warp]
// (2 KB smem, conflict-free) -> 8-way sum -> r_i.
// Column steps: per-thread partial column sums -> g_part (double-buffered)
// -> batch-local monotonic barrier -> per-thread c_reg update.
// Finalize reads the fp16 copy (L2-hot) instead of fp32 s0.

#define BB 32
#define NN 1024
#define MM 1024
#define EPSF 1e-4f
#define KB_ 16            // blocks per batch
#define RPB (NN / KB_)    // 64 rows per block
#define TPB 256

__device__ __half2 g_h[(size_t)BB * NN * MM / 2];   // 64 MB fp16 copy
__device__ float g_part[2][BB * KB_ * MM];          // double-buffered partials
__device__ int g_cnt2[BB];                          // zero-init
__device__ int g_flag[BB];                          // monotonic, persists

// ---------------------------------------------------------------------------
// Batch-local barrier: 16 blocks of batch b. Monotonic target continues from
// the persisted flag value, so graph replays need no reset.
__device__ __forceinline__ void batch_barrier(int b, int& nextv) {
    __threadfence();
    __syncthreads();
    nextv += 1;
    if (threadIdx.x == 0) {
        int old = atomicAdd(&g_cnt2[b], 1);
        if (old == KB_ - 1) {
            atomicExch(&g_cnt2[b], 0);
            __threadfence();
            *(volatile int*)&g_flag[b] = nextv;
        } else {
            while (*(volatile int*)&g_flag[b] - nextv < 0) __nanosleep(32);
        }
        __threadfence();
    }
    __syncthreads();
}

// ---------------------------------------------------------------------------
__global__ void __launch_bounds__(TPB, 4)
sinkhorn_kernel(const float* __restrict__ s, float* __restrict__ out) {
    const int bx = blockIdx.x;
    const int b = bx >> 4;         // batch
    const int k = bx & (KB_ - 1);  // block within batch
    const int tid = threadIdx.x;
    const int warp = tid >> 5;
    const int lane = tid & 31;

    __shared__ float qw[RPB][9];   // row x warp q-partials (padded)
    __shared__ float sr[RPB];      // row scaling r for own rows

    int nextv = *(volatile int*)&g_flag[b];  // barrier base

    const size_t row0 = (size_t)(b * NN + k * RPB);
    const uint2* hrow = (const uint2*)(g_h + row0 * (MM / 2)) + tid;
    const size_t HS2 = MM / 4;     // uint2 per row

    // ---------------- it = 0: fp32->fp16 conversion + column partials (r=1)
    float c_reg[4];
    {
        const float4* sp = (const float4*)(s + row0 * MM) + tid;
        uint2* hw = (uint2*)(g_h + row0 * (MM / 2)) + tid;
        float a0 = 0.f, a1 = 0.f, a2 = 0.f, a3 = 0.f;
#pragma unroll 4
        for (int i = 0; i < RPB; i++) {
            float4 v = sp[(size_t)i * (MM / 4)];
            __half2 h0 = __floats2half2_rn(v.x, v.y);
            __half2 h1 = __floats2half2_rn(v.z, v.w);
            uint2 o;
            o.x = *(unsigned*)&h0;
            o.y = *(unsigned*)&h1;
            hw[(size_t)i * HS2] = o;
            a0 += v.x; a1 += v.y; a2 += v.z; a3 += v.w;
        }
        *(float4*)&g_part[0][((size_t)(b * KB_ + k)) * MM + tid * 4] =
            make_float4(a0, a1, a2, a3);
    }
    batch_barrier(b, nextv);

    // c init (c_old = 1): c = 1 / (P + eps), P from buffer 0 partials.
    {
        float4 p = make_float4(0.f, 0.f, 0.f, 0.f);
#pragma unroll
        for (int q = 0; q < KB_; q++) {
            const float4 v = __ldcg(
                (const float4*)&g_part[0][((size_t)(b * KB_ + q)) * MM + tid * 4]);
            p.x += v.x; p.y += v.y; p.z += v.z; p.w += v.w;
        }
        c_reg[0] = 1.0f / (p.x + EPSF);
        c_reg[1] = 1.0f / (p.y + EPSF);
        c_reg[2] = 1.0f / (p.z + EPSF);
        c_reg[3] = 1.0f / (p.w + EPSF);
    }

    // ---------------- 7 x fused (row step it=2h+1, col step it=2h+2)
    for (int half = 0; half < 7; half++) {
        // ---- row-q sweep: warp partial of q_i = sum_j h_ij * c_j
#pragma unroll 1
        for (int ic = 0; ic < RPB / 4; ic++) {
            uint2 v[4];
#pragma unroll
            for (int ii = 0; ii < 4; ii++)
                v[ii] = hrow[(size_t)(ic * 4 + ii) * HS2];
#pragma unroll
            for (int ii = 0; ii < 4; ii++) {
                float2 f0 = __half22float2(*(__half2*)&v[ii].x);
                float2 f1 = __half22float2(*(__half2*)&v[ii].y);
                float pa = f0.x * c_reg[0];
                float pb = f0.y * c_reg[1];
                pa = fmaf(f1.x, c_reg[2], pa);
                pb = fmaf(f1.y, c_reg[3], pb);
                float p = pa + pb;
#pragma unroll
                for (int o = 16; o > 0; o >>= 1)
                    p += __shfl_xor_sync(0xffffffffu, p, o);
                if (lane == 0) qw[ic * 4 + ii][warp] = p;
            }
        }
        __syncthreads();

        // ---- finish q: 8-way sum per row; update r_i
        if (tid < RPB) {
            const float* qq = qw[tid];
            float q = ((qq[0] + qq[1]) + (qq[2] + qq[3])) +
                      ((qq[4] + qq[5]) + (qq[6] + qq[7]));
            float r = (half == 0) ? 1.0f : sr[tid];
            sr[tid] = r / fmaf(r, q, EPSF);
        }
        __syncthreads();

        // ---- col sweep: acc[e] += r_i * h[i, 4t+e] over own rows
        const int buf = (half + 1) & 1;
        {
            float4 acc = make_float4(0.f, 0.f, 0.f, 0.f);
#pragma unroll 1
            for (int ic = 0; ic < RPB / 8; ic++) {
                uint2 v[8];
#pragma unroll
                for (int ii = 0; ii < 8; ii++)
                    v[ii] = hrow[(size_t)(ic * 8 + ii) * HS2];
#pragma unroll
                for (int ii = 0; ii < 8; ii++) {
                    const float rw = sr[ic * 8 + ii];
                    float2 f0 = __half22float2(*(__half2*)&v[ii].x);
                    float2 f1 = __half22float2(*(__half2*)&v[ii].y);
                    acc.x = fmaf(rw, f0.x, acc.x);
                    acc.y = fmaf(rw, f0.y, acc.y);
                    acc.z = fmaf(rw, f1.x, acc.z);
                    acc.w = fmaf(rw, f1.y, acc.w);
                }
            }
            *(float4*)&g_part[buf][((size_t)(b * KB_ + k)) * MM + tid * 4] =
                acc;
        }
        batch_barrier(b, nextv);

        // ---- c_reg update from buffer `buf` (identical order in all blocks)
        {
            float4 p = make_float4(0.f, 0.f, 0.f, 0.f);
#pragma unroll
            for (int q = 0; q < KB_; q++) {
                const float4 v = __ldcg((const float4*)
                    &g_part[buf][((size_t)(b * KB_ + q)) * MM + tid * 4]);
                p.x += v.x; p.y += v.y; p.z += v.z; p.w += v.w;
            }
            c_reg[0] = c_reg[0] / fmaf(c_reg[0], p.x, EPSF);
            c_reg[1] = c_reg[1] / fmaf(c_reg[1], p.y, EPSF);
            c_reg[2] = c_reg[2] / fmaf(c_reg[2], p.z, EPSF);
            c_reg[3] = c_reg[3] / fmaf(c_reg[3], p.w, EPSF);
        }
    }

    // ---------------- finalize: out = r_i * h_ij * c_j (fp16 copy, L2-hot)
    {
        float4* op = (float4*)(out + row0 * MM) + tid;
#pragma unroll 4
        for (int i = 0; i < RPB; i++) {
            const float r = sr[i];
            uint2 v = hrow[(size_t)i * HS2];
            float2 f0 = __half22float2(*(__half2*)&v.x);
            float2 f1 = __half22float2(*(__half2*)&v.y);
            float4 o;
            o.x = r * f0.x * c_reg[0];
            o.y = r * f0.y * c_reg[1];
            o.z = r * f1.x * c_reg[2];
            o.w = r * f1.y * c_reg[3];
            op[(size_t)i * (MM / 4)] = o;
        }
    }
}

// ---------------------------------------------------------------------------
extern "C" void kernel_launch(void* const* d_in, const int* in_sizes, int n_in,
                              void* d_out, int out_size) {
    const float* s = (const float*)d_in[0];
    float* out = (float*)d_out;
    sinkhorn_kernel<<<BB * KB_, TPB>>>(s, out);
}

// round 8
// speedup vs baseline: 1.0786x; 1.0786x over previous
#include <cuda_runtime.h>
#include <cuda_fp16.h>

// Sinkhorn on s[B=32, N=1024, M=1024], MAX_ITER=15, EPS=1e-4.
//
// Single persistent kernel, factored form s_t = r_i * s0_ij * c_j.
// Block k of batch b owns rows [64k,64k+64) for all phases (block-private
// fp16 slice, L2-resident). Column ownership: thread t owns cols [4t,4t+4)
// (c_reg), published to smem sc[] once per iteration for the row sweep.
// Row sweep: warp-per-8-rows, kk-outer / row-inner so the c slice is loaded
// into registers once per kk; 8 independent uint4 loads per (warp,kk);
// only 40 shuffles per warp per sweep.
// Col sweep: per-thread 4-col partial sums -> g_part (double-buffered) ->
// batch-local monotonic barrier -> c_reg update (identical order everywhere).
// Finalize reads the fp16 copy (L2-hot).

#define BB 32
#define NN 1024
#define MM 1024
#define EPSF 1e-4f
#define KB_ 16            // blocks per batch
#define RPB (NN / KB_)    // 64 rows per block
#define TPB 256

__device__ __half2 g_h[(size_t)BB * NN * MM / 2];   // 64 MB fp16 copy
__device__ float g_part[2][BB * KB_ * MM];          // double-buffered partials
__device__ int g_cnt2[BB];                          // zero-init
__device__ int g_flag[BB];                          // monotonic, persists

// ---------------------------------------------------------------------------
// Batch-local barrier: 16 blocks of batch b. Monotonic target continues from
// the persisted flag value, so graph replays need no reset.
__device__ __forceinline__ void batch_barrier(int b, int& nextv) {
    __threadfence();
    __syncthreads();
    nextv += 1;
    if (threadIdx.x == 0) {
        int old = atomicAdd(&g_cnt2[b], 1);
        if (old == KB_ - 1) {
            atomicExch(&g_cnt2[b], 0);
            __threadfence();
            *(volatile int*)&g_flag[b] = nextv;
        } else {
            while (*(volatile int*)&g_flag[b] - nextv < 0) __nanosleep(32);
        }
        __threadfence();
    }
    __syncthreads();
}

// ---------------------------------------------------------------------------
__global__ void __launch_bounds__(TPB, 4)
sinkhorn_kernel(const float* __restrict__ s, float* __restrict__ out) {
    const int bx = blockIdx.x;
    const int b = bx >> 4;         // batch
    const int k = bx & (KB_ - 1);  // block within batch
    const int tid = threadIdx.x;
    const int warp = tid >> 5;
    const int lane = tid & 31;

    __shared__ float sc[MM];       // column scaling c (published per iter)
    __shared__ float sr[RPB];      // row scaling r for own rows

    int nextv = *(volatile int*)&g_flag[b];  // barrier base

    const size_t row0 = (size_t)(b * NN + k * RPB);
    const uint2* hrow2 = (const uint2*)(g_h + row0 * (MM / 2)) + tid;
    const uint4* h4 = (const uint4*)(g_h + row0 * (MM / 2));
    const size_t HS2 = MM / 4;     // uint2 per row
    const size_t HS4 = MM / 8;     // uint4 per row

    // ---------------- it = 0: fp32->fp16 conversion + column partials (r=1)
    float c_reg[4];
    {
        const float4* sp = (const float4*)(s + row0 * MM) + tid;
        uint2* hw = (uint2*)(g_h + row0 * (MM / 2)) + tid;
        float a0 = 0.f, a1 = 0.f, a2 = 0.f, a3 = 0.f;
#pragma unroll 4
        for (int i = 0; i < RPB; i++) {
            float4 v = __ldcs(sp + (size_t)i * (MM / 4));  // stream fp32
            __half2 h0 = __floats2half2_rn(v.x, v.y);
            __half2 h1 = __floats2half2_rn(v.z, v.w);
            uint2 o;
            o.x = *(unsigned*)&h0;
            o.y = *(unsigned*)&h1;
            hw[(size_t)i * HS2] = o;
            a0 += v.x; a1 += v.y; a2 += v.z; a3 += v.w;
        }
        *(float4*)&g_part[0][((size_t)(b * KB_ + k)) * MM + tid * 4] =
            make_float4(a0, a1, a2, a3);
    }
    batch_barrier(b, nextv);

    // c init (c_old = 1): c = 1 / (P + eps); publish to sc[].
    {
        float4 p = make_float4(0.f, 0.f, 0.f, 0.f);
#pragma unroll
        for (int q = 0; q < KB_; q++) {
            const float4 v = __ldcg(
                (const float4*)&g_part[0][((size_t)(b * KB_ + q)) * MM + tid * 4]);
            p.x += v.x; p.y += v.y; p.z += v.z; p.w += v.w;
        }
        c_reg[0] = 1.0f / (p.x + EPSF);
        c_reg[1] = 1.0f / (p.y + EPSF);
        c_reg[2] = 1.0f / (p.z + EPSF);
        c_reg[3] = 1.0f / (p.w + EPSF);
        *(float4*)&sc[tid * 4] =
            make_float4(c_reg[0], c_reg[1], c_reg[2], c_reg[3]);
    }
    __syncthreads();

    // ---------------- 7 x fused (row step it=2h+1, col step it=2h+2)
    for (int half = 0; half < 7; half++) {
        // ---- row sweep: warp handles rows [8w, 8w+8); kk outer, row inner.
        {
            float acc[8];
#pragma unroll
            for (int rr = 0; rr < 8; rr++) acc[rr] = 0.f;
#pragma unroll
            for (int kk = 0; kk < 4; kk++) {
                const int cu = kk * 32 + lane;       // uint4 column index
                const float4 ca = *(const float4*)&sc[cu * 8];
                const float4 cb = *(const float4*)&sc[cu * 8 + 4];
#pragma unroll
                for (int rr = 0; rr < 8; rr++) {
                    uint4 v = h4[(size_t)(warp * 8 + rr) * HS4 + cu];
                    float2 f0 = __half22float2(*(__half2*)&v.x);
                    float2 f1 = __half22float2(*(__half2*)&v.y);
                    float2 f2 = __half22float2(*(__half2*)&v.z);
                    float2 f3 = __half22float2(*(__half2*)&v.w);
                    float pa = f0.x * ca.x;
                    float pb = f0.y * ca.y;
                    pa = fmaf(f1.x, ca.z, pa);
                    pb = fmaf(f1.y, ca.w, pb);
                    pa = fmaf(f2.x, cb.x, pa);
                    pb = fmaf(f2.y, cb.y, pb);
                    pa = fmaf(f3.x, cb.z, pa);
                    pb = fmaf(f3.y, cb.w, pb);
                    acc[rr] += pa + pb;
                }
            }
#pragma unroll
            for (int rr = 0; rr < 8; rr++) {
                float q = acc[rr];
#pragma unroll
                for (int o = 16; o > 0; o >>= 1)
                    q += __shfl_xor_sync(0xffffffffu, q, o);
                if (lane == 0) {
                    const int i = warp * 8 + rr;
                    float r = (half == 0) ? 1.0f : sr[i];
                    sr[i] = r / fmaf(r, q, EPSF);
                }
            }
        }
        __syncthreads();

        // ---- col sweep: acc[e] += r_i * h[i, 4t+e] over own rows
        const int buf = (half + 1) & 1;
        {
            float4 acc = make_float4(0.f, 0.f, 0.f, 0.f);
#pragma unroll 1
            for (int ic = 0; ic < RPB / 8; ic++) {
                uint2 v[8];
#pragma unroll
                for (int ii = 0; ii < 8; ii++)
                    v[ii] = hrow2[(size_t)(ic * 8 + ii) * HS2];
#pragma unroll
                for (int ii = 0; ii < 8; ii++) {
                    const float rw = sr[ic * 8 + ii];
                    float2 f0 = __half22float2(*(__half2*)&v[ii].x);
                    float2 f1 = __half22float2(*(__half2*)&v[ii].y);
                    acc.x = fmaf(rw, f0.x, acc.x);
                    acc.y = fmaf(rw, f0.y, acc.y);
                    acc.z = fmaf(rw, f1.x, acc.z);
                    acc.w = fmaf(rw, f1.y, acc.w);
                }
            }
            *(float4*)&g_part[buf][((size_t)(b * KB_ + k)) * MM + tid * 4] =
                acc;
        }
        batch_barrier(b, nextv);

        // ---- c_reg update from buffer `buf`; publish to sc[]
        {
            float4 p = make_float4(0.f, 0.f, 0.f, 0.f);
#pragma unroll
            for (int q = 0; q < KB_; q++) {
                const float4 v = __ldcg((const float4*)
                    &g_part[buf][((size_t)(b * KB_ + q)) * MM + tid * 4]);
                p.x += v.x; p.y += v.y; p.z += v.z; p.w += v.w;
            }
            c_reg[0] = c_reg[0] / fmaf(c_reg[0], p.x, EPSF);
            c_reg[1] = c_reg[1] / fmaf(c_reg[1], p.y, EPSF);
            c_reg[2] = c_reg[2] / fmaf(c_reg[2], p.z, EPSF);
            c_reg[3] = c_reg[3] / fmaf(c_reg[3], p.w, EPSF);
            *(float4*)&sc[tid * 4] =
                make_float4(c_reg[0], c_reg[1], c_reg[2], c_reg[3]);
        }
        __syncthreads();
    }

    // ---------------- finalize: out = r_i * h_ij * c_j (fp16 copy, L2-hot)
    {
        float4* op = (float4*)(out + row0 * MM) + tid;
#pragma unroll 4
        for (int i = 0; i < RPB; i++) {
            const float r = sr[i];
            uint2 v = hrow2[(size_t)i * HS2];
            float2 f0 = __half22float2(*(__half2*)&v.x);
            float2 f1 = __half22float2(*(__half2*)&v.y);
            float4 o;
            o.x = r * f0.x * c_reg[0];
            o.y = r * f0.y * c_reg[1];
            o.z = r * f1.x * c_reg[2];
            o.w = r * f1.y * c_reg[3];
            op[(size_t)i * (MM / 4)] = o;
        }
    }
}

// ---------------------------------------------------------------------------
extern "C" void kernel_launch(void* const* d_in, const int* in_sizes, int n_in,
                              void* d_out, int out_size) {
    const float* s = (const float*)d_in[0];
    float* out = (float*)d_out;
    sinkhorn_kernel<<<BB * KB_, TPB>>>(s, out);
}